// round 14
// baseline (speedup 1.0000x reference)
#include <cuda_runtime.h>

// Problem constants (fixed shapes per reference setup_inputs)
#define N_IN   65536
#define BATCH  128
#define N_OUTP 65536
#define M_SAMP 131072   // N_OUT * degree, degree = 2
#define TN     16       // outputs per block in main kernel

// Scratch (device globals: allocation inside kernel_launch is forbidden)
__device__ __align__(16) float g_actT[(size_t)N_IN * BATCH];  // 32 MB transposed, clipped
__device__ int2 g_pairs[M_SAMP];                 // per-sample: {idx*32 (f4 row), bitcast(w)}

// Replicate jnp.linspace(0,1,65536, float32): x[i] = fl(i * fl(1/65535)), x[last]=1.0
__device__ __forceinline__ float gridx(int i) {
    return (i == N_IN - 1) ? 1.0f : (float)i * (1.0f / 65535.0f);
}

// ---------------------------------------------------------------------------
// Kernel 1 (fused): sampling + clip/transpose. float4 both ways via XOR-swizzle.
// (unchanged from measured 10.3us version)
// ---------------------------------------------------------------------------
__global__ void __launch_bounds__(256) prep_kernel(const float* __restrict__ act,
                                                   const float* __restrict__ sp_in) {
    __shared__ __align__(16) float4 tile4[32][32];   // 16 KB
    const int tid = threadIdx.x;
    const int n0  = blockIdx.x * 128;
    const int b0  = blockIdx.y * 32;

    if (tid < 64) {
        int m = (blockIdx.y * gridDim.x + blockIdx.x) * 64 + tid;
        float sp = sp_in[m];
        sp = fminf(fmaxf(sp, 0.0f), 1.0f);
        int i = (int)(sp * 65535.0f);
        i = max(0, min(i, N_IN - 2));
        while (i > 0 && gridx(i) >= sp) --i;
        while (i < N_IN - 2 && gridx(i + 1) < sp) ++i;
        float xi = gridx(i);
        float dx = gridx(i + 1) - xi;
        float w  = (sp - xi) / (dx + 1e-8f);
        g_pairs[m] = make_int2(i * 32, __float_as_int(w));  // pre-scaled float4 row
    }

    const int tx = tid & 31;
    const int ty = tid >> 5;
    const float4* a4 = (const float4*)act;   // row stride N_IN/4 = 16384
#pragma unroll
    for (int j = 0; j < 4; ++j) {
        int brow = ty + 8 * j;
        float4 v = __ldcs(&a4[(size_t)(b0 + brow) * 16384 + (n0 >> 2) + tx]);
        v.x = __saturatef(v.x);
        v.y = __saturatef(v.y);
        v.z = __saturatef(v.z);
        v.w = __saturatef(v.w);
        tile4[brow][tx ^ ((brow >> 2) & 7)] = v;   // STS.128, conflict-free
    }
    __syncthreads();

    const int cx = tid & 7;
    const int n4 = tid >> 3;
    float4 m0 = tile4[4 * cx + 0][n4 ^ cx];   // LDS.128, conflict-free
    float4 m1 = tile4[4 * cx + 1][n4 ^ cx];
    float4 m2 = tile4[4 * cx + 2][n4 ^ cx];
    float4 m3 = tile4[4 * cx + 3][n4 ^ cx];

    float4* t4 = (float4*)g_actT;             // row stride BATCH/4 = 32
    size_t base = (size_t)(n0 + 4 * n4) * 32 + (b0 >> 2) + cx;
    t4[base + 0 * 32] = make_float4(m0.x, m1.x, m2.x, m3.x);
    t4[base + 1 * 32] = make_float4(m0.y, m1.y, m2.y, m3.y);
    t4[base + 2 * 32] = make_float4(m0.z, m1.z, m2.z, m3.z);
    t4[base + 3 * 32] = make_float4(m0.w, m1.w, m2.w, m3.w);
}

// ---------------------------------------------------------------------------
// Kernel 2: main with cp.async.bulk gathers. 128 threads, TN=16 n/block.
// Per n: 2 contiguous 1KB row-pairs (i0,i0+1 and i1,i1+1). 32 bulk copies
// per block, each issued by ONE thread (replaces 512 per-lane cp.asyncs) and
// tracked by one mbarrier via per-thread arrive.expect_tx(1024) before issue.
// Compute + coalesced tile epilogue identical to the measured round-9 kernel.
// ---------------------------------------------------------------------------
__global__ void __launch_bounds__(128) main_kernel(float* __restrict__ out) {
    __shared__ __align__(128) float stage[TN][2][256];   // 32 KB: [n][sample][1KB]
    __shared__ __align__(16)  float tile[TN][130];       // results [n][b]
    __shared__ int4 sp4[TN];
    __shared__ __align__(8) unsigned long long mbar;
    const int tid = threadIdx.x;
    const int w   = tid >> 5;
    const int l   = tid & 31;
    const int n0  = blockIdx.x * TN;

    if (tid < TN) sp4[tid] = ((const int4*)g_pairs)[n0 + tid];
    if (tid == 0) {
        unsigned mb = (unsigned)__cvta_generic_to_shared(&mbar);
        asm volatile("mbarrier.init.shared.b64 [%0], 32;" :: "r"(mb) : "memory");
    }
    __syncthreads();

    // --- issue: 32 threads, one 1KB bulk copy each ---
    if (tid < 32) {
        const int k = tid >> 1;          // which n
        const int s = tid & 1;           // which sample of the pair
        const int4 sp = sp4[k];
        const size_t off = (size_t)(s ? sp.z : sp.x) * 16;   // i*32*16 = i*512 bytes
        const char* src = (const char*)g_actT + off;         // rows i, i+1 (1KB)
        unsigned mb = (unsigned)__cvta_generic_to_shared(&mbar);
        unsigned d  = (unsigned)__cvta_generic_to_shared(&stage[k][s][0]);
        asm volatile("mbarrier.arrive.expect_tx.shared.b64 _, [%0], 1024;"
                     :: "r"(mb) : "memory");
        asm volatile("cp.async.bulk.shared::cluster.global.mbarrier::complete_tx::bytes "
                     "[%0], [%1], 1024, [%2];"
                     :: "r"(d), "l"(src), "r"(mb) : "memory");
    }

    // --- wait for all 32KB (acquire: we read other threads' data) ---
    {
        unsigned mb = (unsigned)__cvta_generic_to_shared(&mbar);
        asm volatile(
            "{\n\t"
            ".reg .pred P;\n\t"
            "WAIT_%=:\n\t"
            "mbarrier.try_wait.parity.acquire.cta.shared::cta.b64 P, [%0], 0;\n\t"
            "@!P bra WAIT_%=;\n\t"
            "}"
            :: "r"(mb) : "memory");
    }

    // --- compute: warp w handles n-offsets w*4..w*4+3 ---
#pragma unroll
    for (int j = 0; j < 4; ++j) {
        const int k = w * 4 + j;
        const int4 s = sp4[k];
        const float w0 = __int_as_float(s.y);
        const float w1 = __int_as_float(s.w);
        const float4* p = (const float4*)&stage[k][0][0];  // 4 rows x 32 f4
        float4 a00 = p[l];
        float4 a01 = p[32 + l];
        float4 a10 = p[64 + l];
        float4 a11 = p[96 + l];

        float4 r;
        r.x = (1.0f - fmaf(a01.x - a00.x, w0, a00.x)) * (1.0f - fmaf(a11.x - a10.x, w1, a10.x));
        r.y = (1.0f - fmaf(a01.y - a00.y, w0, a00.y)) * (1.0f - fmaf(a11.y - a10.y, w1, a10.y));
        r.z = (1.0f - fmaf(a01.z - a00.z, w0, a00.z)) * (1.0f - fmaf(a11.z - a10.z, w1, a10.z));
        r.w = (1.0f - fmaf(a01.w - a00.w, w0, a00.w)) * (1.0f - fmaf(a11.w - a10.w, w1, a10.w));

        float* d0 = &tile[k][4 * l];
        *(float2*)d0       = make_float2(r.x, r.y);
        *(float2*)(d0 + 2) = make_float2(r.z, r.w);
    }
    __syncthreads();

    // --- epilogue: coalesced streaming writes, float2 over n ---
    const int c2 = tid & 7;              // n-pair: cols 2c2, 2c2+1 (16 n -> 8 pairs)
    const int rb = tid >> 3;             // 0..15
    for (int r = rb; r < BATCH; r += 16) {
        float2 v;
        v.x = tile[2 * c2 + 0][r];
        v.y = tile[2 * c2 + 1][r];
        float2* dst = (float2*)&out[(size_t)r * N_OUTP + n0 + 2 * c2];
        __stcs(dst, v);
    }
}

// ---------------------------------------------------------------------------
extern "C" void kernel_launch(void* const* d_in, const int* in_sizes, int n_in,
                              void* d_out, int out_size) {
    const float* act = (const float*)d_in[0];   // (128, 65536) f32
    const float* sp  = (const float*)d_in[1];   // (65536, 2, 1) f32
    float* out       = (float*)d_out;           // (128, 65536) f32

    prep_kernel<<<dim3(N_IN / 128, BATCH / 32), 256>>>(act, sp);
    main_kernel<<<N_OUTP / TN, 128>>>(out);
}

// round 15
// speedup vs baseline: 1.1361x; 1.1361x over previous
#include <cuda_runtime.h>

// Problem constants (fixed shapes per reference setup_inputs)
#define N_IN   65536
#define BATCH  128
#define N_OUTP 65536
#define M_SAMP 131072   // N_OUT * degree, degree = 2
#define TN     16       // outputs per block in main kernel

// Scratch (device globals: allocation inside kernel_launch is forbidden)
__device__ __align__(16) float g_actT[(size_t)N_IN * BATCH];  // 32 MB transposed, clipped
__device__ int2 g_pairs[M_SAMP];                 // per-sample: {idx, bitcast(w)}

// Replicate jnp.linspace(0,1,65536, float32): x[i] = fl(i * fl(1/65535)), x[last]=1.0
__device__ __forceinline__ float gridx(int i) {
    return (i == N_IN - 1) ? 1.0f : (float)i * (1.0f / 65535.0f);
}

// ---------------------------------------------------------------------------
// Kernel 1 (fused): sampling + clip/transpose, double-tile for 8-deep MLP.
// Grid (256, 4), 256 threads. Block tile: n 256 x b 32. 128 samples/block.
// Two XOR-swizzled float4 tiles; all 8 LDG.128 per thread in flight at once.
// ---------------------------------------------------------------------------
__global__ void __launch_bounds__(256) prep_kernel(const float* __restrict__ act,
                                                   const float* __restrict__ sp_in) {
    // logical (b, c4) lives at tile[b][c4 ^ ((b>>2) & 7)]
    __shared__ __align__(16) float4 tileA[32][32];   // n0 .. n0+127
    __shared__ __align__(16) float4 tileB[32][32];   // n0+128 .. n0+255
    const int tid = threadIdx.x;
    const int n0  = blockIdx.x * 256;
    const int b0  = blockIdx.y * 32;

    // --- sampling: 128 samples per block ---
    if (tid < 128) {
        int m = (blockIdx.y * gridDim.x + blockIdx.x) * 128 + tid;
        float sp = sp_in[m];
        sp = fminf(fmaxf(sp, 0.0f), 1.0f);
        int i = (int)(sp * 65535.0f);
        i = max(0, min(i, N_IN - 2));
        // Exact searchsorted-left fix-up: largest i with x[i] < sp (clamped)
        while (i > 0 && gridx(i) >= sp) --i;
        while (i < N_IN - 2 && gridx(i + 1) < sp) ++i;
        float xi = gridx(i);
        float dx = gridx(i + 1) - xi;
        float w  = (sp - xi) / (dx + 1e-8f);
        g_pairs[m] = make_int2(i, __float_as_int(w));
    }

    // --- load: thread (tx=c4 0..31, ty 0..7), 8 LDG.128 in flight ---
    const int tx = tid & 31;
    const int ty = tid >> 5;
    const float4* a4 = (const float4*)act;   // row stride N_IN/4 = 16384
#pragma unroll
    for (int j = 0; j < 4; ++j) {
        int brow = ty + 8 * j;               // local b: 0..31
        size_t rowb = (size_t)(b0 + brow) * 16384 + (n0 >> 2);
        float4 va = __ldcs(&a4[rowb + tx]);
        float4 vb = __ldcs(&a4[rowb + 32 + tx]);
        va.x = __saturatef(va.x); va.y = __saturatef(va.y);
        va.z = __saturatef(va.z); va.w = __saturatef(va.w);
        vb.x = __saturatef(vb.x); vb.y = __saturatef(vb.y);
        vb.z = __saturatef(vb.z); vb.w = __saturatef(vb.w);
        int sc = tx ^ ((brow >> 2) & 7);
        tileA[brow][sc] = va;                // STS.128, conflict-free
        tileB[brow][sc] = vb;
    }
    __syncthreads();

    // --- store: thread (cx 0..7, n4 0..31), 4x4 micro-transpose per tile ---
    const int cx = tid & 7;                   // b-quad: batches b0+4cx..4cx+3
    const int n4 = tid >> 3;                  // n-quad within 128-wide tile
    float4* t4 = (float4*)g_actT;             // row stride BATCH/4 = 32
#pragma unroll
    for (int t = 0; t < 2; ++t) {
        float4 m0, m1, m2, m3;
        if (t == 0) {
            m0 = tileA[4 * cx + 0][n4 ^ cx];  // LDS.128, conflict-free
            m1 = tileA[4 * cx + 1][n4 ^ cx];
            m2 = tileA[4 * cx + 2][n4 ^ cx];
            m3 = tileA[4 * cx + 3][n4 ^ cx];
        } else {
            m0 = tileB[4 * cx + 0][n4 ^ cx];
            m1 = tileB[4 * cx + 1][n4 ^ cx];
            m2 = tileB[4 * cx + 2][n4 ^ cx];
            m3 = tileB[4 * cx + 3][n4 ^ cx];
        }
        size_t base = (size_t)(n0 + 128 * t + 4 * n4) * 32 + (b0 >> 2) + cx;
        t4[base + 0 * 32] = make_float4(m0.x, m1.x, m2.x, m3.x);
        t4[base + 1 * 32] = make_float4(m0.y, m1.y, m2.y, m3.y);
        t4[base + 2 * 32] = make_float4(m0.z, m1.z, m2.z, m3.z);
        t4[base + 3 * 32] = make_float4(m0.w, m1.w, m2.w, m3.w);
    }
}

// ---------------------------------------------------------------------------
// Kernel 2: main — EXACT round-9 measured-best (22.08us). cp.async-staged
// gathers; lane l copies bytes [16l,16l+16) of each 512B row and reads back
// exactly those bytes -> wait_group alone guarantees visibility.
// ---------------------------------------------------------------------------
__global__ void __launch_bounds__(128) main_kernel(float* __restrict__ out) {
    __shared__ __align__(16) float stage[TN][4][BATCH];  // 32 KB gather staging
    __shared__ __align__(16) float tile[TN][130];        // results [n][b]
    __shared__ int4 sp4[TN];             // {i0, w0, i1, w1} per output n
    const int tid = threadIdx.x;
    const int w   = tid >> 5;            // warp 0..3
    const int l   = tid & 31;            // lane
    const int n0  = blockIdx.x * TN;

    if (tid < TN) sp4[tid] = ((const int4*)g_pairs)[n0 + tid];
    __syncthreads();

    // --- issue phase: 2 commit-groups of 2 n each (16 rows total per warp) ---
    const char* actB = (const char*)g_actT;
#pragma unroll
    for (int g = 0; g < 2; ++g) {
#pragma unroll
        for (int j = 0; j < 2; ++j) {
            const int k = w * 4 + g * 2 + j;
            const int4 s = sp4[k];
            const char* p0 = actB + (size_t)s.x * 512 + l * 16;  // rows i0, i0+1
            const char* p1 = actB + (size_t)s.z * 512 + l * 16;  // rows i1, i1+1
            unsigned d = (unsigned)__cvta_generic_to_shared(&stage[k][0][0]) + l * 16;
            asm volatile("cp.async.cg.shared.global [%0], [%1], 16;\n" :: "r"(d),        "l"(p0));
            asm volatile("cp.async.cg.shared.global [%0], [%1], 16;\n" :: "r"(d +  512), "l"(p0 + 512));
            asm volatile("cp.async.cg.shared.global [%0], [%1], 16;\n" :: "r"(d + 1024), "l"(p1));
            asm volatile("cp.async.cg.shared.global [%0], [%1], 16;\n" :: "r"(d + 1536), "l"(p1 + 512));
        }
        asm volatile("cp.async.commit_group;\n" ::);
    }

    // --- compute phase: overlap group 1 flight with group 0 compute ---
#pragma unroll
    for (int g = 0; g < 2; ++g) {
        if (g == 0) asm volatile("cp.async.wait_group 1;\n" ::);
        else        asm volatile("cp.async.wait_group 0;\n" ::);
        __syncwarp();
#pragma unroll
        for (int j = 0; j < 2; ++j) {
            const int k = w * 4 + g * 2 + j;
            const int4 s = sp4[k];
            const float w0 = __int_as_float(s.y);
            const float w1 = __int_as_float(s.w);
            const float4* p = (const float4*)&stage[k][0][0];  // 4 rows x 32 f4
            float4 a00 = p[l];
            float4 a01 = p[32 + l];
            float4 a10 = p[64 + l];
            float4 a11 = p[96 + l];

            float4 r;
            r.x = (1.0f - fmaf(a01.x - a00.x, w0, a00.x)) * (1.0f - fmaf(a11.x - a10.x, w1, a10.x));
            r.y = (1.0f - fmaf(a01.y - a00.y, w0, a00.y)) * (1.0f - fmaf(a11.y - a10.y, w1, a10.y));
            r.z = (1.0f - fmaf(a01.z - a00.z, w0, a00.z)) * (1.0f - fmaf(a11.z - a10.z, w1, a10.z));
            r.w = (1.0f - fmaf(a01.w - a00.w, w0, a00.w)) * (1.0f - fmaf(a11.w - a10.w, w1, a10.w));

            float* d0 = &tile[k][4 * l];
            *(float2*)d0       = make_float2(r.x, r.y);
            *(float2*)(d0 + 2) = make_float2(r.z, r.w);
        }
    }
    __syncthreads();

    // --- epilogue: coalesced streaming writes, float2 over n ---
    const int c2 = tid & 7;              // n-pair: cols 2c2, 2c2+1 (16 n -> 8 pairs)
    const int rb = tid >> 3;             // 0..15
    for (int r = rb; r < BATCH; r += 16) {
        float2 v;
        v.x = tile[2 * c2 + 0][r];
        v.y = tile[2 * c2 + 1][r];
        float2* dst = (float2*)&out[(size_t)r * N_OUTP + n0 + 2 * c2];
        __stcs(dst, v);
    }
}

// ---------------------------------------------------------------------------
extern "C" void kernel_launch(void* const* d_in, const int* in_sizes, int n_in,
                              void* d_out, int out_size) {
    const float* act = (const float*)d_in[0];   // (128, 65536) f32
    const float* sp  = (const float*)d_in[1];   // (65536, 2, 1) f32
    float* out       = (float*)d_out;           // (128, 65536) f32

    prep_kernel<<<dim3(N_IN / 256, BATCH / 32), 256>>>(act, sp);
    main_kernel<<<N_OUTP / TN, 128>>>(out);
}